// round 13
// baseline (speedup 1.0000x reference)
#include <cuda_runtime.h>
#include <cuda_fp16.h>
#include <cstdint>
#include <math.h>

#define T_TOK 8192          // 4 * 2048 tokens
#define HDIM  2048
#define FDIM  4096          // 2*H

// ---------------- static device scratch (no allocs allowed) ----------------
__device__ int g_cnt[2];
__device__ int g_idx[2][T_TOK];
__device__ __half g_xh[(size_t)T_TOK * HDIM];
__device__ __half g_w0a[(size_t)FDIM * HDIM], g_w1a[(size_t)FDIM * HDIM];
__device__ __half g_w0b[(size_t)HDIM * FDIM], g_w1b[(size_t)HDIM * FDIM];
__device__ __half g_hh[(size_t)T_TOK * FDIM];

// ---------------- PTX helpers (base ISA only — no 'a'-gated features) ------
__device__ __forceinline__ uint32_t smem_u32(const void* p) {
    uint32_t a;
    asm("{ .reg .u64 t; cvta.to.shared.u64 t, %1; cvt.u32.u64 %0, t; }" : "=r"(a) : "l"(p));
    return a;
}
__device__ __forceinline__ void cp16(uint32_t dst, const void* src, uint32_t sz) {
    asm volatile("cp.async.cg.shared.global [%0], [%1], 16, %2;"
                 :: "r"(dst), "l"(src), "r"(sz) : "memory");
}
__device__ __forceinline__ void cp_commit() {
    asm volatile("cp.async.commit_group;" ::: "memory");
}
template <int N>
__device__ __forceinline__ void cp_wait() {
    asm volatile("cp.async.wait_group %0;" :: "n"(N) : "memory");
}
__device__ __forceinline__ void ldm4(uint32_t* r, uint32_t addr) {
    asm volatile("ldmatrix.sync.aligned.m8n8.x4.shared.b16 {%0,%1,%2,%3}, [%4];"
                 : "=r"(r[0]), "=r"(r[1]), "=r"(r[2]), "=r"(r[3]) : "r"(addr));
}
__device__ __forceinline__ void mma16816(float* d, const uint32_t* a, const uint32_t* b) {
    asm volatile(
        "mma.sync.aligned.m16n8k16.row.col.f32.f16.f16.f32 "
        "{%0,%1,%2,%3}, {%4,%5,%6,%7}, {%8,%9}, {%0,%1,%2,%3};"
        : "+f"(d[0]), "+f"(d[1]), "+f"(d[2]), "+f"(d[3])
        : "r"(a[0]), "r"(a[1]), "r"(a[2]), "r"(a[3]), "r"(b[0]), "r"(b[1]));
}
__device__ __forceinline__ uint32_t pack_h(__half a, __half b) {
    return (uint32_t)__half_as_ushort(a) | ((uint32_t)__half_as_ushort(b) << 16);
}

// ---------------- small kernels ---------------------------------------------
__global__ void zero_cnt_kernel() {
    if (threadIdx.x < 2) g_cnt[threadIdx.x] = 0;
}

// Fused gate + fp16 convert of x. One warp per token. argmax over 2 logits
// (softmax monotone; tie -> expert 0, matching jnp.argmax-first).
__global__ void gate_split_kernel(const float* __restrict__ x,
                                  const float* __restrict__ Wg,
                                  __half* __restrict__ xh) {
    __shared__ float swg[2 * HDIM];
    int tid = threadIdx.x;
    for (int i = tid; i < 2 * HDIM; i += blockDim.x) swg[i] = Wg[i];
    __syncthreads();
    int warp = tid >> 5, lane = tid & 31;
    int tok = blockIdx.x * 8 + warp;
    size_t rowOff = (size_t)tok * HDIM;
    const float4* xr = (const float4*)(x + rowOff);
    uint2* hh = (uint2*)(xh + rowOff);

    float a0 = 0.f, a1 = 0.f;
#pragma unroll
    for (int j = 0; j < HDIM / 128; ++j) {        // 16 iters of float4 per lane
        int i4 = lane + 32 * j;
        float4 v = xr[i4];
        int k = i4 * 4;
        a0 = fmaf(v.x, swg[k], fmaf(v.y, swg[k + 1], fmaf(v.z, swg[k + 2], fmaf(v.w, swg[k + 3], a0))));
        a1 = fmaf(v.x, swg[HDIM + k], fmaf(v.y, swg[HDIM + k + 1],
             fmaf(v.z, swg[HDIM + k + 2], fmaf(v.w, swg[HDIM + k + 3], a1))));
        hh[i4] = make_uint2(pack_h(__float2half(v.x), __float2half(v.y)),
                            pack_h(__float2half(v.z), __float2half(v.w)));
    }
#pragma unroll
    for (int o = 16; o; o >>= 1) {
        a0 += __shfl_xor_sync(0xffffffffu, a0, o);
        a1 += __shfl_xor_sync(0xffffffffu, a1, o);
    }
    if (lane == 0) {
        int e = (a1 > a0) ? 1 : 0;
        int pos = atomicAdd(&g_cnt[e], 1);
        g_idx[e][pos] = tok;
    }
}

// fp32 -> fp16 weight convert; blockIdx.z selects which of two tensors.
__global__ void splitW_kernel(const float* __restrict__ s0, __half* __restrict__ d0,
                              const float* __restrict__ s1, __half* __restrict__ d1,
                              int n4) {
    int i = blockIdx.x * blockDim.x + threadIdx.x;
    if (i >= n4) return;
    const float* src = blockIdx.z ? s1 : s0;
    __half* dst = blockIdx.z ? d1 : d0;
    float4 v = ((const float4*)src)[i];
    ((uint2*)dst)[i] = make_uint2(pack_h(__float2half(v.x), __float2half(v.y)),
                                  pack_h(__float2half(v.z), __float2half(v.w)));
}

template <int ACT>
__device__ __forceinline__ float act_fn(float v) {
    if (ACT == 0) return 0.5f * v * (1.0f + erff(v * 0.70710678118654752440f)); // exact GELU
    if (ACT == 1) return fmaxf(v, 0.0f);                                        // ReLU
    return v;
}

// ---------------- mma.sync gathered GEMM ------------------------------------
// C[tok, n] = act_e( sum_k A[tok,k]*B_e[n,k] + bias_e[n] ), e = blockIdx.z,
// A rows via g_idx[e]. Single-term fp16 (A, B both fp16; fp32 accum).
// CTA tile 128x128, BK=64, 8 warps (2M x 4N), warp tile 64x32.
// Smem per stage: A/B, 128 rows x 128B each (32 KB); 3 stages, 2 CTA/SM.
static constexpr int GBM = 128, GBN = 128, GBK = 64;
static constexpr uint32_t STAGE_BYTES = 2 * 128 * 128;       // 32 KB
static constexpr uint32_t GEMM_SMEM = 3 * STAGE_BYTES;       // 96 KB dynamic

// ACT0/ACT1: activation for expert0/expert1 (up: GELU/ReLU; down: none/none)
template <int ACT0, int ACT1, bool HALF_OUT>
__global__ void __launch_bounds__(256, 2)
gemm_mma(const __half* __restrict__ A,
         const __half* __restrict__ B0, const __half* __restrict__ B1,
         const float* __restrict__ bias0, const float* __restrict__ bias1,
         float* __restrict__ Cf, __half* __restrict__ Ch,
         int K, int ldc) {
    extern __shared__ char dyn_smem[];
    __shared__ int   sTok[GBM];
    __shared__ float sBias[GBN];

    const int expert = blockIdx.z;
    const int n_e = g_cnt[expert];
    const int mBase = blockIdx.y * GBM;
    if (mBase >= n_e) return;
    const int nBase = blockIdx.x * GBN;
    const __half* B = expert ? B1 : B0;
    const float* bias = expert ? bias1 : bias0;
    const uint32_t sb = smem_u32(dyn_smem);
    const int tid = threadIdx.x;

    if (tid < GBM) {
        int r = mBase + tid;
        sTok[tid] = (r < n_e) ? g_idx[expert][r] : -1;
    }
    if (tid < GBN) sBias[tid] = bias[nBase + tid];
    __syncthreads();

    const int nCh = K / GBK;

    // 1024 16B-chunks per matrix; row = i>>3, c = i&7, swizzle c^(row&7)
    auto load_stage = [&](int c, int buf) {
        const int kOff = c * GBK;
        const uint32_t aS = sb + buf * STAGE_BYTES;
        const uint32_t bS = aS + 16384;
#pragma unroll
        for (int it = 0; it < 4; ++it) {
            int i = tid + it * 256;
            int row = i >> 3, cc = i & 7;
            uint32_t so = (uint32_t)(row * 128 + ((cc ^ (row & 7)) << 4));
            int tok = sTok[row];
            uint32_t sz = (tok >= 0) ? 16u : 0u;
            int tokc = (tok >= 0) ? tok : 0;
            const char* pA = (const char*)(A + (size_t)tokc * K + kOff) + cc * 16;
            cp16(aS + so, pA, sz);
            const char* pB = (const char*)(B + (size_t)(nBase + row) * K + kOff) + cc * 16;
            cp16(bS + so, pB, 16u);
        }
        cp_commit();
    };

    // fragment lane mapping
    const int lane = tid & 31;
    const int wid = tid >> 5;
    const int wm = wid & 1;       // M
    const int wn = wid >> 1;      // N
    const int aRow = lane & 15;
    const int aSel = (lane >> 4) & 1;
    const int aSw  = aRow & 7;
    const int bRow = (lane & 7) + ((lane >> 4) & 1) * 8;
    const int bSel = (lane >> 3) & 1;
    const int bSw  = bRow & 7;

    uint32_t aRowByte[4], bRowByte[2];
#pragma unroll
    for (int mi = 0; mi < 4; ++mi) aRowByte[mi] = (uint32_t)((wm * 64 + mi * 16 + aRow) * 128);
#pragma unroll
    for (int nb = 0; nb < 2; ++nb) bRowByte[nb] = (uint32_t)((wn * 32 + nb * 16 + bRow) * 128);

    float acc[4][4][4];
#pragma unroll
    for (int mi = 0; mi < 4; ++mi)
#pragma unroll
        for (int ni = 0; ni < 4; ++ni)
#pragma unroll
            for (int q = 0; q < 4; ++q) acc[mi][ni][q] = 0.f;

    // 3-stage pipeline
    load_stage(0, 0);
    load_stage(1, 1);
    for (int c = 0; c < nCh; ++c) {
        if (c + 2 < nCh) {
            load_stage(c + 2, (c + 2) % 3);
            cp_wait<2>();
        } else {
            cp_wait<0>();
        }
        __syncthreads();

        const uint32_t aS = sb + (c % 3) * STAGE_BYTES;
        const uint32_t bS = aS + 16384;

#pragma unroll
        for (int ks = 0; ks < GBK / 16; ++ks) {
            const int kc = ks * 2;
            const uint32_t aOff = (uint32_t)(((kc + aSel) ^ aSw) << 4);
            const uint32_t bOff = (uint32_t)(((kc + bSel) ^ bSw) << 4);
            uint32_t bh[2][4];
#pragma unroll
            for (int nb = 0; nb < 2; ++nb) ldm4(bh[nb], bS + bRowByte[nb] + bOff);
#pragma unroll
            for (int mi = 0; mi < 4; ++mi) {
                uint32_t af[4];
                ldm4(af, aS + aRowByte[mi] + aOff);
#pragma unroll
                for (int nb = 0; nb < 2; ++nb)
#pragma unroll
                    for (int h = 0; h < 2; ++h)
                        mma16816(acc[mi][nb * 2 + h], af, &bh[nb][h * 2]);
            }
        }
        __syncthreads();
    }

    // epilogue: d0,d1 -> (m = lane/4, n = 2*(lane%4)); d2,d3 -> m+8
    const int mrow = lane >> 2;
    const int ncol = 2 * (lane & 3);
#pragma unroll
    for (int mi = 0; mi < 4; ++mi) {
#pragma unroll
        for (int ni = 0; ni < 4; ++ni) {
            int colLoc = wn * 32 + ni * 8 + ncol;
            int col = nBase + colLoc;
            float bv0 = sBias[colLoc], bv1 = sBias[colLoc + 1];
            int rLoc = wm * 64 + mi * 16 + mrow;
            int tok0 = sTok[rLoc], tok1 = sTok[rLoc + 8];
#pragma unroll
            for (int half = 0; half < 2; ++half) {
                int tok = half ? tok1 : tok0;
                if (tok < 0) continue;
                float r0 = acc[mi][ni][half * 2 + 0] + bv0;
                float r1 = acc[mi][ni][half * 2 + 1] + bv1;
                float v0 = expert ? act_fn<ACT1>(r0) : act_fn<ACT0>(r0);
                float v1 = expert ? act_fn<ACT1>(r1) : act_fn<ACT0>(r1);
                size_t base = (size_t)tok * ldc + col;
                if (HALF_OUT) {
                    *(uint32_t*)(Ch + base) = pack_h(__float2half(v0), __float2half(v1));
                } else {
                    *(float2*)(Cf + base) = make_float2(v0, v1);
                }
            }
        }
    }
}

// ---------------- launch -----------------------------------------------------
extern "C" void kernel_launch(void* const* d_in, const int* in_sizes, int n_in,
                              void* d_out, int out_size) {
    (void)in_sizes; (void)n_in; (void)out_size;
    const float* x   = (const float*)d_in[0];
    const float* Wg  = (const float*)d_in[1];
    const float* W0a = (const float*)d_in[2];
    const float* b0a = (const float*)d_in[3];
    const float* W0b = (const float*)d_in[4];
    const float* b0b = (const float*)d_in[5];
    const float* W1a = (const float*)d_in[6];
    const float* b1a = (const float*)d_in[7];
    const float* W1b = (const float*)d_in[8];
    const float* b1b = (const float*)d_in[9];
    float* out = (float*)d_out;

    __half *xh, *w0a, *w1a, *w0b, *w1b, *hh;
    cudaGetSymbolAddress((void**)&xh, g_xh);
    cudaGetSymbolAddress((void**)&w0a, g_w0a); cudaGetSymbolAddress((void**)&w1a, g_w1a);
    cudaGetSymbolAddress((void**)&w0b, g_w0b); cudaGetSymbolAddress((void**)&w1b, g_w1b);
    cudaGetSymbolAddress((void**)&hh, g_hh);

    cudaFuncSetAttribute(gemm_mma<0, 1, true>,  cudaFuncAttributeMaxDynamicSharedMemorySize, GEMM_SMEM);
    cudaFuncSetAttribute(gemm_mma<2, 2, false>, cudaFuncAttributeMaxDynamicSharedMemorySize, GEMM_SMEM);

    zero_cnt_kernel<<<1, 32>>>();
    gate_split_kernel<<<T_TOK / 8, 256>>>(x, Wg, xh);

    {
        int n4 = FDIM * HDIM / 4;
        dim3 g(n4 / 256, 1, 2);
        splitW_kernel<<<g, 256>>>(W0a, w0a, W1a, w1a, n4);
        splitW_kernel<<<g, 256>>>(W0b, w0b, W1b, w1b, n4);
    }

    dim3 blk(256);
    dim3 gUp(FDIM / GBN, T_TOK / GBM, 2);   // (32, 64, 2), early-exit on n_e
    dim3 gDn(HDIM / GBN, T_TOK / GBM, 2);   // (16, 64, 2)

    // up-projection + activation -> h (fp16); both experts in one launch
    gemm_mma<0, 1, true><<<gUp, blk, GEMM_SMEM>>>(xh, w0a, w1a, b0a, b1a,
                                                  nullptr, hh, HDIM, FDIM);
    // down-projection -> out (fp32); both experts, each token written once
    gemm_mma<2, 2, false><<<gDn, blk, GEMM_SMEM>>>(hh, w0b, w1b, b0b, b1b,
                                                   out, nullptr, FDIM, HDIM);
}